// round 10
// baseline (speedup 1.0000x reference)
#include <cuda_runtime.h>
#include <cuda_bf16.h>

// DistortionLoss (eff_distloss) — fully fused, O(1) last-block tail.
//
// R9 -> R10: the 4.2us finalize node is pure launch overhead. Fuse it into
// the main kernel with the ticket pattern, but unlike R2/R3 (whose last block
// looped over 4096 L2 doubles, ~7us serialized) the tail here is O(1):
//  - each block: REDG atomicAdd(&g_accum, partial); __threadfence();
//    atomicInc ticket (wraps to 0 -> self-resetting, no init kernel).
//  - last block: atomicExch(&g_accum, 0.0) reads the coherent total AND
//    resets the accumulator for the next graph replay in one L2 atomic,
//    then writes the scaled fp32 output.
// Main loop unchanged (pair-unrolled, 6 independent LDG.128/iter, 4096x256).

#define LOSS_WEIGHT 0.01f
#define N_SAMPLES 128
#define GRID_MAX 4096
#define BLOCK_THREADS 256

__device__ double   g_accum = 0.0;  // returns to 0 every launch
__device__ unsigned g_ticket = 0;   // wraps to 0 every launch

__device__ __forceinline__ float row_contrib(
    const float4 wv, const float4 mv, const float4 sv, const int lane)
{
    // uni term partial: sum s*w^2 over this lane's 4 elements
    float uni = sv.x * wv.x * wv.x;
    uni = fmaf(sv.y * wv.y, wv.y, uni);
    uni = fmaf(sv.z * wv.z, wv.z, uni);
    uni = fmaf(sv.w * wv.w, wv.w, uni);

    // wm = w * m
    const float wm0 = wv.x * mv.x;
    const float wm1 = wv.y * mv.y;
    const float wm2 = wv.z * mv.z;
    const float wm3 = wv.w * mv.w;

    // local exclusive prefixes within the 4-element chunk
    const float eW1 = wv.x;
    const float eW2 = eW1 + wv.y;
    const float eW3 = eW2 + wv.z;
    const float tW  = eW3 + wv.w;     // lane total of w

    const float eM1 = wm0;
    const float eM2 = eM1 + wm1;
    const float eM3 = eM2 + wm2;
    const float tM  = eM3 + wm3;      // lane total of wm

    // warp inclusive scan of lane totals (w and wm together; independent
    // chains pipeline their SHFL latencies)
    float iW = tW, iM = tM;
    #pragma unroll
    for (int off = 1; off < 32; off <<= 1) {
        const float aW = __shfl_up_sync(0xffffffffu, iW, off);
        const float aM = __shfl_up_sync(0xffffffffu, iM, off);
        if (lane >= off) { iW += aW; iM += aM; }
    }
    const float EW = iW - tW;   // exclusive warp prefix of w
    const float EM = iM - tM;   // exclusive warp prefix of wm

    // bi term: sum_k wm_k * exW_k - w_k * exWM_k  (exclusive prefixes)
    float bi;
    bi  = wm0 * EW          - wv.x * EM;
    bi += wm1 * (EW + eW1)  - wv.y * (EM + eM1);
    bi += wm2 * (EW + eW2)  - wv.z * (EM + eM2);
    bi += wm3 * (EW + eW3)  - wv.w * (EM + eM3);

    return (1.0f / 3.0f) * uni + 2.0f * bi;
}

__global__ __launch_bounds__(BLOCK_THREADS) void dl_fused_kernel(
    const float* __restrict__ w,
    const float* __restrict__ m,
    const float* __restrict__ s,
    float* __restrict__ out,
    int B, float scale)
{
    const int lane   = threadIdx.x & 31;
    const int warpIn = threadIdx.x >> 5;
    const int gwarp  = (blockIdx.x * BLOCK_THREADS + threadIdx.x) >> 5;
    const int nwarps = (gridDim.x * BLOCK_THREADS) >> 5;

    float acc = 0.0f;

    // Row-pair loop: warp handles rows (2g, 2g+1), stride 2*nwarps.
    int row = 2 * gwarp;
    for (; row + 1 < B; row += 2 * nwarps) {
        const size_t b0 = (size_t)row * N_SAMPLES;
        const size_t b1 = b0 + N_SAMPLES;
        // 6 independent 16B loads issued before any compute
        const float4 wv0 = reinterpret_cast<const float4*>(w + b0)[lane];
        const float4 wv1 = reinterpret_cast<const float4*>(w + b1)[lane];
        const float4 mv0 = reinterpret_cast<const float4*>(m + b0)[lane];
        const float4 mv1 = reinterpret_cast<const float4*>(m + b1)[lane];
        const float4 sv0 = reinterpret_cast<const float4*>(s + b0)[lane];
        const float4 sv1 = reinterpret_cast<const float4*>(s + b1)[lane];

        acc += row_contrib(wv0, mv0, sv0, lane);
        acc += row_contrib(wv1, mv1, sv1, lane);
    }
    if (row < B) {  // odd-B tail
        const size_t b0 = (size_t)row * N_SAMPLES;
        const float4 wv0 = reinterpret_cast<const float4*>(w + b0)[lane];
        const float4 mv0 = reinterpret_cast<const float4*>(m + b0)[lane];
        const float4 sv0 = reinterpret_cast<const float4*>(s + b0)[lane];
        acc += row_contrib(wv0, mv0, sv0, lane);
    }

    // warp reduce
    #pragma unroll
    for (int off = 16; off > 0; off >>= 1)
        acc += __shfl_down_sync(0xffffffffu, acc, off);

    __shared__ float warp_sums[BLOCK_THREADS / 32];
    if (lane == 0) warp_sums[warpIn] = acc;
    __syncthreads();

    if (threadIdx.x == 0) {
        float blockAcc = 0.0f;
        #pragma unroll
        for (int i = 0; i < BLOCK_THREADS / 32; i++) blockAcc += warp_sums[i];

        atomicAdd(&g_accum, (double)blockAcc);   // REDG, single address
        __threadfence();                          // order add before ticket
        const unsigned ticket = atomicInc(&g_ticket, gridDim.x - 1);
        if (ticket == gridDim.x - 1) {
            // Last block: read total coherently AND reset accumulator for
            // the next graph replay, in one L2 atomic.
            const unsigned long long totBits = atomicExch(
                reinterpret_cast<unsigned long long*>(&g_accum),
                0ull);
            const double total = __longlong_as_double((long long)totBits);
            out[0] = (float)(total * (double)scale);
        }
    }
}

extern "C" void kernel_launch(void* const* d_in, const int* in_sizes, int n_in,
                              void* d_out, int out_size) {
    const float* w = (const float*)d_in[0];
    const float* m = (const float*)d_in[1];
    const float* s = (const float*)d_in[2];
    float* out = (float*)d_out;

    const int B = in_sizes[0] / N_SAMPLES;

    const int warpsPerBlock = BLOCK_THREADS / 32;
    const int maxUseful = (B + 1) / 2;              // row pairs
    int blocks = GRID_MAX;
    if (blocks * warpsPerBlock > maxUseful) {
        blocks = (maxUseful + warpsPerBlock - 1) / warpsPerBlock;
        if (blocks < 1) blocks = 1;
    }

    dl_fused_kernel<<<blocks, BLOCK_THREADS>>>(w, m, s, out, B,
                                               LOSS_WEIGHT / (float)B);
}

// round 12
// speedup vs baseline: 1.1404x; 1.1404x over previous
#include <cuda_runtime.h>
#include <cuda_bf16.h>

// DistortionLoss (eff_distloss) — two-kernel (R9 structure), quad-unrolled.
//
// R10 -> R11: fusion regressed in all 5 attempts regardless of occupancy;
// two-kernel R9 (REDG accumulate + O(1) self-resetting finalize) is the
// keeper. This round pushes main-loop bandwidth 6.94 -> ~7.3 TB/s via
// UNROLL-4: each warp loads 12 independent float4 (four consecutive rows x
// three arrays) before any compute. In-flight bytes/SM rises ~33% even
// though occupancy drops (~50%) — DRAM-bound kernels care about bytes in
// flight, not warps.

#define LOSS_WEIGHT 0.01f
#define N_SAMPLES 128
#define GRID_MAX 4096
#define BLOCK_THREADS 256

__device__ double g_accum = 0.0;   // always 0 between launches

__device__ __forceinline__ float row_contrib(
    const float4 wv, const float4 mv, const float4 sv, const int lane)
{
    // uni term partial: sum s*w^2 over this lane's 4 elements
    float uni = sv.x * wv.x * wv.x;
    uni = fmaf(sv.y * wv.y, wv.y, uni);
    uni = fmaf(sv.z * wv.z, wv.z, uni);
    uni = fmaf(sv.w * wv.w, wv.w, uni);

    // wm = w * m
    const float wm0 = wv.x * mv.x;
    const float wm1 = wv.y * mv.y;
    const float wm2 = wv.z * mv.z;
    const float wm3 = wv.w * mv.w;

    // local exclusive prefixes within the 4-element chunk
    const float eW1 = wv.x;
    const float eW2 = eW1 + wv.y;
    const float eW3 = eW2 + wv.z;
    const float tW  = eW3 + wv.w;     // lane total of w

    const float eM1 = wm0;
    const float eM2 = eM1 + wm1;
    const float eM3 = eM2 + wm2;
    const float tM  = eM3 + wm3;      // lane total of wm

    // warp inclusive scan of lane totals (w and wm together; independent
    // chains pipeline their SHFL latencies)
    float iW = tW, iM = tM;
    #pragma unroll
    for (int off = 1; off < 32; off <<= 1) {
        const float aW = __shfl_up_sync(0xffffffffu, iW, off);
        const float aM = __shfl_up_sync(0xffffffffu, iM, off);
        if (lane >= off) { iW += aW; iM += aM; }
    }
    const float EW = iW - tW;   // exclusive warp prefix of w
    const float EM = iM - tM;   // exclusive warp prefix of wm

    // bi term: sum_k wm_k * exW_k - w_k * exWM_k  (exclusive prefixes)
    float bi;
    bi  = wm0 * EW          - wv.x * EM;
    bi += wm1 * (EW + eW1)  - wv.y * (EM + eM1);
    bi += wm2 * (EW + eW2)  - wv.z * (EM + eM2);
    bi += wm3 * (EW + eW3)  - wv.w * (EM + eM3);

    return (1.0f / 3.0f) * uni + 2.0f * bi;
}

__global__ __launch_bounds__(BLOCK_THREADS) void dl_main_kernel(
    const float* __restrict__ w,
    const float* __restrict__ m,
    const float* __restrict__ s,
    int B)
{
    const int lane   = threadIdx.x & 31;
    const int warpIn = threadIdx.x >> 5;
    const int gwarp  = (blockIdx.x * BLOCK_THREADS + threadIdx.x) >> 5;
    const int nwarps = (gridDim.x * BLOCK_THREADS) >> 5;

    float acc = 0.0f;

    // Quad-row loop: warp handles rows (4g..4g+3), stride 4*nwarps.
    int row = 4 * gwarp;
    for (; row + 3 < B; row += 4 * nwarps) {
        const size_t b0 = (size_t)row * N_SAMPLES;
        const size_t b1 = b0 + N_SAMPLES;
        const size_t b2 = b1 + N_SAMPLES;
        const size_t b3 = b2 + N_SAMPLES;
        // 12 independent 16B loads issued before any compute
        const float4 wv0 = reinterpret_cast<const float4*>(w + b0)[lane];
        const float4 wv1 = reinterpret_cast<const float4*>(w + b1)[lane];
        const float4 wv2 = reinterpret_cast<const float4*>(w + b2)[lane];
        const float4 wv3 = reinterpret_cast<const float4*>(w + b3)[lane];
        const float4 mv0 = reinterpret_cast<const float4*>(m + b0)[lane];
        const float4 mv1 = reinterpret_cast<const float4*>(m + b1)[lane];
        const float4 mv2 = reinterpret_cast<const float4*>(m + b2)[lane];
        const float4 mv3 = reinterpret_cast<const float4*>(m + b3)[lane];
        const float4 sv0 = reinterpret_cast<const float4*>(s + b0)[lane];
        const float4 sv1 = reinterpret_cast<const float4*>(s + b1)[lane];
        const float4 sv2 = reinterpret_cast<const float4*>(s + b2)[lane];
        const float4 sv3 = reinterpret_cast<const float4*>(s + b3)[lane];

        acc += row_contrib(wv0, mv0, sv0, lane);
        acc += row_contrib(wv1, mv1, sv1, lane);
        acc += row_contrib(wv2, mv2, sv2, lane);
        acc += row_contrib(wv3, mv3, sv3, lane);
    }
    for (; row < B; row++) {  // tail rows
        const size_t b0 = (size_t)row * N_SAMPLES;
        const float4 wv0 = reinterpret_cast<const float4*>(w + b0)[lane];
        const float4 mv0 = reinterpret_cast<const float4*>(m + b0)[lane];
        const float4 sv0 = reinterpret_cast<const float4*>(s + b0)[lane];
        acc += row_contrib(wv0, mv0, sv0, lane);
    }

    // warp reduce
    #pragma unroll
    for (int off = 16; off > 0; off >>= 1)
        acc += __shfl_down_sync(0xffffffffu, acc, off);

    __shared__ float warp_sums[BLOCK_THREADS / 32];
    if (lane == 0) warp_sums[warpIn] = acc;
    __syncthreads();

    if (threadIdx.x == 0) {
        float blockAcc = 0.0f;
        #pragma unroll
        for (int i = 0; i < BLOCK_THREADS / 32; i++) blockAcc += warp_sums[i];
        atomicAdd(&g_accum, (double)blockAcc);   // REDG, single address
    }
}

__global__ void dl_finalize_kernel(float* __restrict__ out, float scale) {
    out[0] = (float)(g_accum * (double)scale);
    g_accum = 0.0;   // leave accumulator clean for the next replay
}

extern "C" void kernel_launch(void* const* d_in, const int* in_sizes, int n_in,
                              void* d_out, int out_size) {
    const float* w = (const float*)d_in[0];
    const float* m = (const float*)d_in[1];
    const float* s = (const float*)d_in[2];
    float* out = (float*)d_out;

    const int B = in_sizes[0] / N_SAMPLES;

    const int warpsPerBlock = BLOCK_THREADS / 32;
    const int maxUseful = (B + 3) / 4;              // row quads
    int blocks = GRID_MAX;
    if (blocks * warpsPerBlock > maxUseful) {
        blocks = (maxUseful + warpsPerBlock - 1) / warpsPerBlock;
        if (blocks < 1) blocks = 1;
    }

    dl_main_kernel<<<blocks, BLOCK_THREADS>>>(w, m, s, B);
    dl_finalize_kernel<<<1, 1>>>(out, LOSS_WEIGHT / (float)B);
}